// round 4
// baseline (speedup 1.0000x reference)
#include <cuda_runtime.h>
#include <cuda_bf16.h>
#include <cstdint>
#include <cstddef>

// VectorQuantizer on GB300 (sm_103a)
// HMMA (mma.sync bf16) 2-split/3-term GEMM + exact fp32 rescue of tight margins.
// z_e: (16,256,64,64) fp32 ; embedding: (1024,256) fp32

#define NEMB 1024
#define EDIM 256
#define HW   4096
#define NPIX 65536
#define NC   16777216

#define MARGIN  2e-2f
#define FLAGCAP 8192

// ---- device scratch ----
__device__ __align__(128) __nv_bfloat16 g_A[2][(size_t)NPIX * EDIM];  // [split][pix*256+k]
__device__ __align__(128) __nv_bfloat16 g_Bv[2][NEMB * EDIM];         // [split][code*256+k]
__device__ __align__(16) float  g_e2[NEMB];
__device__ int    g_idx[NPIX];
__device__ double g_part[2048];
__device__ int    g_nflag;
__device__ int    g_flag[FLAGCAP];

// ---- helpers ----
static __device__ __forceinline__ uint32_t s2u(const void* p) {
    uint32_t a;
    asm("{ .reg .u64 t; cvta.to.shared.u64 t, %1; cvt.u32.u64 %0, t; }" : "=r"(a) : "l"(p));
    return a;
}
static __device__ __forceinline__ void cpa16(uint32_t dst, const void* src) {
    asm volatile("cp.async.cg.shared.global [%0], [%1], 16;" :: "r"(dst), "l"(src));
}
static __device__ __forceinline__ void split2(float x, __nv_bfloat16& h0, __nv_bfloat16& h1) {
    h0 = __float2bfloat16(x);
    h1 = __float2bfloat16(x - __bfloat162float(h0));
}

#define LDSM_X4(r0, r1, r2, r3, a) \
    asm volatile("ldmatrix.sync.aligned.m8n8.x4.shared.b16 {%0,%1,%2,%3}, [%4];" \
                 : "=r"(r0), "=r"(r1), "=r"(r2), "=r"(r3) : "r"(a))
#define MMA16816(d, a, b0, b1) \
    asm volatile("mma.sync.aligned.m16n8k16.row.col.f32.bf16.bf16.f32 " \
                 "{%0,%1,%2,%3}, {%4,%5,%6,%7}, {%8,%9}, {%0,%1,%2,%3};" \
                 : "+f"((d)[0]), "+f"((d)[1]), "+f"((d)[2]), "+f"((d)[3]) \
                 : "r"((a)[0]), "r"((a)[1]), "r"((a)[2]), "r"((a)[3]), "r"(b0), "r"(b1))

// ============================================================
// K1: split z_e into 2 bf16 planes, transposed to [pix][k].
// ============================================================
__global__ __launch_bounds__(256) void k_split(const float* __restrict__ z) {
    __shared__ float sz[32][257];
    const int t = threadIdx.x;
    const int pix0 = blockIdx.x << 5;
    const float* zb = z + (((size_t)(pix0 >> 12)) << 20) + (pix0 & 4095);

    if (blockIdx.x == 0 && t == 0) g_nflag = 0;

    #pragma unroll 8
    for (int it = 0; it < 32; ++it) {
        int slot = t + (it << 8);
        int k = slot >> 5, p = slot & 31;
        sz[p][k] = zb[(size_t)k * HW + p];
    }
    __syncthreads();

    #pragma unroll
    for (int it = 0; it < 4; ++it) {
        int g = t + (it << 8);
        int p = g >> 5, k0 = (g & 31) << 3;
        union { __nv_bfloat16 h[8]; uint4 v; } u0, u1;
        #pragma unroll
        for (int j = 0; j < 8; ++j) split2(sz[p][k0 + j], u0.h[j], u1.h[j]);
        size_t dst = ((size_t)(pix0 + p) << 8) + k0;
        *reinterpret_cast<uint4*>(&g_A[0][dst]) = u0.v;
        *reinterpret_cast<uint4*>(&g_A[1][dst]) = u1.v;
    }
}

// ============================================================
// K2: embedding -> 2 bf16 splits + exact fp32 norms.
// ============================================================
__global__ __launch_bounds__(256) void k_prep_e(const float* __restrict__ emb) {
    int warp = (blockIdx.x * blockDim.x + threadIdx.x) >> 5;
    int lane = threadIdx.x & 31;
    if (warp >= NEMB) return;
    const float* row = emb + (size_t)warp * EDIM;
    int k0 = lane << 3;
    float4 v0 = *reinterpret_cast<const float4*>(row + k0);
    float4 v1 = *reinterpret_cast<const float4*>(row + k0 + 4);
    float xs[8] = {v0.x, v0.y, v0.z, v0.w, v1.x, v1.y, v1.z, v1.w};
    union { __nv_bfloat16 h[8]; uint4 v; } u0, u1;
    float s = 0.f;
    #pragma unroll
    for (int j = 0; j < 8; ++j) {
        s += xs[j] * xs[j];
        split2(xs[j], u0.h[j], u1.h[j]);
    }
    size_t dst = ((size_t)warp << 8) + k0;
    *reinterpret_cast<uint4*>(&g_Bv[0][dst]) = u0.v;
    *reinterpret_cast<uint4*>(&g_Bv[1][dst]) = u1.v;
    #pragma unroll
    for (int o = 16; o; o >>= 1) s += __shfl_xor_sync(0xFFFFFFFFu, s, o);
    if (lane == 0) g_e2[warp] = s;
}

// ============================================================
// K3: HMMA GEMM + fused argmin.
// CTA = 128 pixels; warp owns 16 rows. 8 N-chunks of 128 codes,
// 16 K-steps of 16, double-buffered cp.async.
// smem rows: 64B payload (2 splits x 16 bf16), 80B pitch (conflict-free).
// ============================================================
__global__ __launch_bounds__(256, 2) void k_mma() {
    __shared__ __align__(16) char sA[2][128 * 80];
    __shared__ __align__(16) char sB[2][128 * 80];
    __shared__ float se2[NEMB];

    const int t = threadIdx.x;
    const int wid = t >> 5;
    const int lane = t & 31;
    const int pix0 = blockIdx.x << 7;

    #pragma unroll
    for (int i = 0; i < 4; ++i) se2[t + (i << 8)] = g_e2[t + (i << 8)];

    const uint32_t sAu = s2u(sA);
    const uint32_t sBu = s2u(sB);

    // --- cp.async role: threads 0-127 load A rows, 128-255 load B rows ---
    const bool isB = t >= 128;
    const int  row = t & 127;
    const __nv_bfloat16* P0 = isB ? g_Bv[0] : g_A[0];
    const __nv_bfloat16* P1 = isB ? g_Bv[1] : g_A[1];
    const size_t rbase = isB ? ((size_t)row << 8) : ((size_t)(pix0 + row) << 8);
    const uint32_t dbase = (isB ? sBu : sAu) + row * 80;

    // --- ldmatrix per-lane addresses (byte offsets within buffer) ---
    const uint32_t aoff = (uint32_t)((wid * 16 + (lane & 15)) * 80 + ((lane >> 4) << 4));
    const int nl = (lane & 7) + ((lane >> 4) << 3);
    const int kh = (lane >> 3) & 1;
    const uint32_t boff = (uint32_t)(nl * 80 + kh * 16);

    float rbv[2] = {3.402823466e38f, 3.402823466e38f};
    float rb2[2] = {3.402823466e38f, 3.402823466e38f};
    int   rbi[2] = {0, 0};

    float acc[16][4];

    // prime the pipeline: step 0 (kc=0, cc=0) into buffer 0
    {
        cpa16(dbase + 0,  &P0[rbase + 0]);
        cpa16(dbase + 16, &P0[rbase + 8]);
        cpa16(dbase + 32, &P1[rbase + 0]);
        cpa16(dbase + 48, &P1[rbase + 8]);
        asm volatile("cp.async.commit_group;" ::: "memory");
    }

    #pragma unroll 1
    for (int g = 0; g < 128; ++g) {
        const int buf = g & 1;
        if (g < 127) {
            const int gn = g + 1;
            const int cc = gn >> 4, kc = gn & 15;
            const size_t off = rbase + (isB ? ((size_t)cc << 15) : 0) + (kc << 4);
            const uint32_t d = dbase + ((gn & 1) ? 10240u : 0u);
            cpa16(d + 0,  &P0[off]);
            cpa16(d + 16, &P0[off + 8]);
            cpa16(d + 32, &P1[off]);
            cpa16(d + 48, &P1[off + 8]);
            asm volatile("cp.async.commit_group;" ::: "memory");
            asm volatile("cp.async.wait_group 1;" ::: "memory");
        } else {
            asm volatile("cp.async.wait_group 0;" ::: "memory");
        }
        __syncthreads();

        if ((g & 15) == 0) {
            #pragma unroll
            for (int n = 0; n < 16; ++n)
                #pragma unroll
                for (int j = 0; j < 4; ++j) acc[n][j] = 0.f;
        }

        // ---- compute this k-step ----
        const uint32_t ab = sAu + (buf ? 10240u : 0u) + aoff;
        uint32_t a0[4], a1[4];
        LDSM_X4(a0[0], a0[1], a0[2], a0[3], ab);        // split 0
        LDSM_X4(a1[0], a1[1], a1[2], a1[3], ab + 32);   // split 1

        const uint32_t bb = sBu + (buf ? 10240u : 0u) + boff;
        #pragma unroll
        for (int p = 0; p < 8; ++p) {
            uint32_t b0[4], b1[4];
            LDSM_X4(b0[0], b0[1], b0[2], b0[3], bb + p * (16 * 80));       // split 0
            LDSM_X4(b1[0], b1[1], b1[2], b1[3], bb + p * (16 * 80) + 32);  // split 1
            // n-frag 2p   : {b[0], b[1]} ; n-frag 2p+1 : {b[2], b[3]}
            MMA16816(acc[2 * p],     a0, b0[0], b0[1]);
            MMA16816(acc[2 * p],     a1, b0[0], b0[1]);
            MMA16816(acc[2 * p],     a0, b1[0], b1[1]);
            MMA16816(acc[2 * p + 1], a0, b0[2], b0[3]);
            MMA16816(acc[2 * p + 1], a1, b0[2], b0[3]);
            MMA16816(acc[2 * p + 1], a0, b1[2], b1[3]);
        }
        __syncthreads();

        // ---- epilogue at the end of each 128-code chunk ----
        if ((g & 15) == 15) {
            const int codebase = (g >> 4) << 7;
            #pragma unroll
            for (int slot = 0; slot < 2; ++slot) {
                float bv = rbv[slot], b2 = rb2[slot];
                int   bi = rbi[slot];
                #pragma unroll
                for (int n = 0; n < 16; ++n) {
                    int c0 = codebase + n * 8 + (lane & 3) * 2;
                    float s0 = fmaf(-2.f, acc[n][slot * 2],     se2[c0]);
                    float s1 = fmaf(-2.f, acc[n][slot * 2 + 1], se2[c0 + 1]);
                    if (s0 < bv) { b2 = bv; bv = s0; bi = c0; } else if (s0 < b2) b2 = s0;
                    if (s1 < bv) { b2 = bv; bv = s1; bi = c0 + 1; } else if (s1 < b2) b2 = s1;
                }
                rbv[slot] = bv; rb2[slot] = b2; rbi[slot] = bi;
            }
        }
    }

    // ---- cross-lane merge over the 4 lanes sharing each row ----
    #pragma unroll
    for (int o = 1; o <= 2; o <<= 1) {
        #pragma unroll
        for (int slot = 0; slot < 2; ++slot) {
            float ov = __shfl_xor_sync(0xFFFFFFFFu, rbv[slot], o);
            float o2 = __shfl_xor_sync(0xFFFFFFFFu, rb2[slot], o);
            int   oi = __shfl_xor_sync(0xFFFFFFFFu, rbi[slot], o);
            if (ov < rbv[slot] || (ov == rbv[slot] && oi < rbi[slot])) {
                rb2[slot] = fminf(rbv[slot], o2);
                rbv[slot] = ov; rbi[slot] = oi;
            } else {
                rb2[slot] = fminf(rb2[slot], ov);
            }
        }
    }
    if ((lane & 3) == 0) {
        #pragma unroll
        for (int slot = 0; slot < 2; ++slot) {
            int prow = pix0 + wid * 16 + (lane >> 2) + slot * 8;
            g_idx[prow] = rbi[slot];
            if (rb2[slot] - rbv[slot] < MARGIN) {
                int pos = atomicAdd(&g_nflag, 1);
                if (pos < FLAGCAP) g_flag[pos] = prow;
            }
        }
    }
}

// ============================================================
// K4: exact fp32 rescore of margin-flagged pixels (one warp each)
// ============================================================
__global__ __launch_bounds__(256) void k_fix(const float* __restrict__ z,
                                             const float* __restrict__ emb) {
    __shared__ float sx[8][256];
    const int w = threadIdx.x >> 5, lane = threadIdx.x & 31;
    int n = g_nflag; if (n > FLAGCAP) n = FLAGCAP;
    for (int f = blockIdx.x * 8 + w; f < n; f += gridDim.x * 8) {
        int pix = g_flag[f];
        const float* zb = z + (((size_t)(pix >> 12)) << 20) + (pix & 4095);
        for (int k = lane; k < EDIM; k += 32) sx[w][k] = zb[(size_t)k * HW];
        __syncwarp();
        float bv = 3.402823466e38f; int bi = 0;
        for (int c = lane; c < NEMB; c += 32) {
            const float* e = emb + (size_t)c * EDIM;
            float a0 = 0.f, a1 = 0.f, a2 = 0.f, a3 = 0.f;
            #pragma unroll 8
            for (int k = 0; k < EDIM; k += 4) {
                a0 = fmaf(sx[w][k],     e[k],     a0);
                a1 = fmaf(sx[w][k + 1], e[k + 1], a1);
                a2 = fmaf(sx[w][k + 2], e[k + 2], a2);
                a3 = fmaf(sx[w][k + 3], e[k + 3], a3);
            }
            float sc = g_e2[c] - 2.f * ((a0 + a1) + (a2 + a3));
            if (sc < bv) { bv = sc; bi = c; }
        }
        #pragma unroll
        for (int o = 16; o; o >>= 1) {
            float ov = __shfl_xor_sync(0xFFFFFFFFu, bv, o);
            int   oi = __shfl_xor_sync(0xFFFFFFFFu, bi, o);
            if (ov < bv || (ov == bv && oi < bi)) { bv = ov; bi = oi; }
        }
        if (lane == 0) g_idx[pix] = bi;
        __syncwarp();
    }
}

// ============================================================
// K5: gather z_q, write z_q_st = z_e + (z_q - z_e), loss partials
// ============================================================
__global__ __launch_bounds__(256)
void k_gather(const float* __restrict__ z, const float* __restrict__ emb,
              float* __restrict__ out) {
    __shared__ float sE[32 * 260];
    __shared__ float swarp[8];
    const int t = threadIdx.x;
    const int pix0 = blockIdx.x << 5;

    #pragma unroll
    for (int it = 0; it < 8; ++it) {
        int slot = t + (it << 8);
        int p = slot >> 6, c4 = slot & 63;
        int idx = g_idx[pix0 + p];
        float4 v = *reinterpret_cast<const float4*>(emb + (size_t)idx * EDIM + (c4 << 2));
        *reinterpret_cast<float4*>(&sE[p * 260 + (c4 << 2)]) = v;
    }
    __syncthreads();

    const float* zb = z   + (((size_t)(pix0 >> 12)) << 20) + (pix0 & 4095);
    float*       ob = out + (((size_t)(pix0 >> 12)) << 20) + (pix0 & 4095);

    float lsum = 0.f;
    #pragma unroll
    for (int it = 0; it < 8; ++it) {
        int slot = t + (it << 8);
        int hw = slot & 31, c4 = slot >> 5;
        float4 e = *reinterpret_cast<const float4*>(&sE[hw * 260 + (c4 << 2)]);
        float ev[4] = {e.x, e.y, e.z, e.w};
        #pragma unroll
        for (int j = 0; j < 4; ++j) {
            size_t gg = (size_t)((c4 << 2) + j) * HW + hw;
            float ze = zb[gg];
            float d = ev[j] - ze;
            ob[gg] = ze + d;
            lsum += d * d;
        }
    }
    #pragma unroll
    for (int o = 16; o; o >>= 1) lsum += __shfl_xor_sync(0xFFFFFFFFu, lsum, o);
    if ((t & 31) == 0) swarp[t >> 5] = lsum;
    __syncthreads();
    if (t == 0) {
        double s = 0.0;
        #pragma unroll
        for (int w = 0; w < 8; ++w) s += (double)swarp[w];
        g_part[blockIdx.x] = s;
    }
}

// ============================================================
// K6: loss finalize
// ============================================================
__global__ void k_loss(float* __restrict__ out, int out_size) {
    __shared__ double sd[256];
    int t = threadIdx.x;
    double s = 0.0;
    for (int i = t; i < 2048; i += 256) s += g_part[i];
    sd[t] = s;
    __syncthreads();
    for (int o = 128; o; o >>= 1) {
        if (t < o) sd[t] += sd[t + o];
        __syncthreads();
    }
    if (t == 0 && out_size > NC)
        out[NC] = (float)(0.25 * sd[0] / (double)NC);
}

// ============================================================
extern "C" void kernel_launch(void* const* d_in, const int* in_sizes, int n_in,
                              void* d_out, int out_size) {
    const float* z   = (const float*)d_in[0];
    const float* emb = (const float*)d_in[1];
    float* out = (float*)d_out;

    k_split <<<2048, 256>>>(z);
    k_prep_e<<<128,  256>>>(emb);
    k_mma   <<<512,  256>>>();
    k_fix   <<<32,   256>>>(z, emb);
    k_gather<<<2048, 256>>>(z, emb, out);
    k_loss  <<<1,    256>>>(out, out_size);
}